// round 3
// baseline (speedup 1.0000x reference)
#include <cuda_runtime.h>

#define B 8
#define P 2048
#define D 1024
#define E 16
#define S 64
#define DK 128
#define H 16

typedef unsigned long long ull;

// ---------------- scratch (static device globals; no allocation) ----------------
__device__ float g_xa[(size_t)B * P * 2 * S];   // active-slice layernorm output (8 MB)
__device__ float g_V[(size_t)B * P * 2 * DK];   // per-(token,slot) V vectors (16 MB)
__device__ float g_fused[B * P];
__device__ float g_we[E];
__device__ float g_aw[E];
__device__ float g_invt;
__device__ float g_dirs[E * 5 * DK];
__device__ int   g_cnt[E];
__device__ int   g_list[E * P];                 // p | (slot<<16)
__device__ int   g_pe[P * 2];                   // active experts per p (-1 = none)
__device__ float g_den[P];

// ---------------- f32x2 packed-FMA helpers ----------------
__device__ __forceinline__ ull pk2(float lo, float hi) {
    ull r;
    asm("mov.b64 %0, {%1, %2};" : "=l"(r) : "f"(lo), "f"(hi));
    return r;
}
__device__ __forceinline__ void fma2(ull &c, ull a, ull b) {
    asm("fma.rn.f32x2 %0, %1, %2, %3;" : "=l"(c) : "l"(a), "l"(b), "l"(c));
}
__device__ __forceinline__ float2 upk2(ull v) {
    float lo, hi;
    asm("mov.b64 {%0, %1}, %2;" : "=f"(lo), "=f"(hi) : "l"(v));
    return make_float2(lo, hi);
}

__device__ __forceinline__ float sigmf(float x) { return 1.0f / (1.0f + expf(-x)); }

// ---------------- K0: per-expert scalars, dirs, zero counters ----------------
__global__ void k_setup(const float* __restrict__ alpha, const float* __restrict__ betas,
                        const float* __restrict__ pos_embed, const float* __restrict__ penta,
                        const float* __restrict__ temp) {
    int t = threadIdx.x;
    if (t < E) {
        g_cnt[t] = 0;
        g_aw[t] = sigmf(alpha[t]);
        float s = 0.0f;
        for (int d = 0; d < DK; d++) s += pos_embed[t * DK + d];
        float pw = sigmf(s * (1.0f / DK));
        const int offs[4] = {-2, -1, 1, 2};
        float vw = 0.0f; int vc = 0;
        for (int j = 0; j < 4; j++) {
            int nb = t + offs[j];
            if (nb >= 0 && nb < E) { vw += sigmf(betas[t * 4 + j]); vc++; }
        }
        g_we[t] = pw * (1.0f + vw / (float)vc);
    }
    if (t == 0) g_invt = 1.0f / fabsf(temp[0]);
    if (t < E * 5) {  // 80 dir rows
        const float* row = penta + (size_t)t * DK;
        float ss = 0.0f;
        for (int d = 0; d < DK; d++) ss += row[d] * row[d];
        float rn = rsqrtf(ss);
        for (int d = 0; d < DK; d++) g_dirs[t * DK + d] = row[d] * rn;
    }
}

// ---------------- K1: binning by fingerprint band ----------------
__global__ void k_bin(const float* __restrict__ fps) {
    int p = blockIdx.x * blockDim.x + threadIdx.x;
    if (p >= P) return;
    float fp = fps[p];
    int e0 = -1, e1 = -1;
    float den = 0.0f;
    for (int e = 0; e < E; e++) {
        float mn = fmaxf(0.0f, e * 0.0625f - 0.03125f);
        float mx = fminf(1.0f, (e + 1) * 0.0625f + 0.03125f);
        if (fp >= mn && fp < mx) {
            den += g_we[e];
            int slot;
            if (e0 < 0) { e0 = e; slot = 0; } else { e1 = e; slot = 1; }
            int pos = atomicAdd(&g_cnt[e], 1);
            g_list[e * P + pos] = p | (slot << 16);
        }
    }
    g_pe[p * 2] = e0;
    g_pe[p * 2 + 1] = e1;
    g_den[p] = fmaxf(den, 1e-6f);
}

// ---------------- K2: layernorm; out=x copy; write active xn slices ----------------
__global__ void __launch_bounds__(256) k_ln(const float* __restrict__ x,
                                            const float* __restrict__ gamma,
                                            const float* __restrict__ beta,
                                            float* __restrict__ out) {
    int warp = threadIdx.x >> 5, lane = threadIdx.x & 31;
    int tok = blockIdx.x * 8 + warp;          // 0..B*P-1
    const float4* xr = (const float4*)(x + (size_t)tok * D);
    float4 v[8];
    float sum = 0.0f;
#pragma unroll
    for (int k = 0; k < 8; k++) {
        v[k] = xr[k * 32 + lane];
        sum += v[k].x + v[k].y + v[k].z + v[k].w;
    }
#pragma unroll
    for (int o = 16; o; o >>= 1) sum += __shfl_xor_sync(0xffffffffu, sum, o);
    float mu = sum * (1.0f / D);
    float vs = 0.0f;
#pragma unroll
    for (int k = 0; k < 8; k++) {
        float dx = v[k].x - mu, dy = v[k].y - mu, dz = v[k].z - mu, dw = v[k].w - mu;
        vs += dx * dx + dy * dy + dz * dz + dw * dw;
    }
#pragma unroll
    for (int o = 16; o; o >>= 1) vs += __shfl_xor_sync(0xffffffffu, vs, o);
    float rstd = rsqrtf(vs * (1.0f / D) + 1e-5f);

    float4* orow = (float4*)(out + (size_t)tok * D);
#pragma unroll
    for (int k = 0; k < 8; k++) orow[k * 32 + lane] = v[k];   // residual base

    int p = tok & (P - 1);
#pragma unroll
    for (int slot = 0; slot < 2; slot++) {
        int e = g_pe[p * 2 + slot];
        if (e < 0) continue;
        int fbase = e * 16;              // float4 index of slice start
        int kk = fbase >> 5;
        int l0 = fbase & 31;
        if (lane >= l0 && lane < l0 + 16) {
            int f = fbase + (lane - l0);
            float4 xv = v[kk];
            float4 gm = ((const float4*)gamma)[f];
            float4 bt = ((const float4*)beta)[f];
            float4 o;
            o.x = (xv.x - mu) * rstd * gm.x + bt.x;
            o.y = (xv.y - mu) * rstd * gm.y + bt.y;
            o.z = (xv.z - mu) * rstd * gm.z + bt.z;
            o.w = (xv.w - mu) * rstd * gm.w + bt.w;
            ((float4*)g_xa)[((size_t)tok * 2 + slot) * 16 + (lane - l0)] = o;
        }
    }
}

// ---------------- K3: per-expert gate + V GEMM (gathered) ----------------
__global__ void __launch_bounds__(256, 2) k_gatev(const float* __restrict__ w1,
                                                  const float* __restrict__ b1,
                                                  const float* __restrict__ w2,
                                                  const float* __restrict__ b2,
                                                  const float* __restrict__ wv) {
    int e = blockIdx.y;
    int base = blockIdx.x * 16;
    int cnt = g_cnt[e];
    if (base >= cnt) return;

    __shared__ float a[128 * 65];
    __shared__ float gs[128];
    __shared__ int sp[16];
    __shared__ int ssl[16];
    int tid = threadIdx.x;

    if (tid < 16) {
        int idx = base + tid;
        if (idx < cnt) {
            int v = g_list[e * P + idx];
            sp[tid] = v & 0xFFFF;
            ssl[tid] = v >> 16;
        } else { sp[tid] = -1; ssl[tid] = 0; }
    }
    __syncthreads();

    // stage gathered xn slices: 128 rows x 64 (row = entry*8 + b), padded stride 65
    {
        int r = tid >> 1, hf = tid & 1;
        int p = sp[r >> 3];
        float* arow = a + r * 65 + hf * 32;
        if (p >= 0) {
            int b = r & 7, sl = ssl[r >> 3];
            const float4* src = (const float4*)(g_xa + (((size_t)(b * P + p)) * 2 + sl) * S) + hf * 8;
#pragma unroll
            for (int k = 0; k < 8; k++) {
                float4 w = src[k];
                arow[k * 4 + 0] = w.x; arow[k * 4 + 1] = w.y;
                arow[k * 4 + 2] = w.z; arow[k * 4 + 3] = w.w;
            }
        } else {
#pragma unroll
            for (int k = 0; k < 32; k++) arow[k] = 0.0f;
        }
    }
    __syncthreads();

    // alpha gate: one thread per row
    if (tid < 128) {
        float h[16];
#pragma unroll
        for (int j = 0; j < H; j++) h[j] = b1[e * H + j];
        const float* ar = a + tid * 65;
        const float* w1r = w1 + (size_t)e * S * H;
        for (int s = 0; s < S; s++) {
            float av = ar[s];
            const float* wr = w1r + s * H;
#pragma unroll
            for (int j = 0; j < H; j++) h[j] += av * wr[j];
        }
        float gacc = b2[e];
#pragma unroll
        for (int j = 0; j < H; j++) {
            float hv = h[j];
            float ge = 0.5f * hv * (1.0f + erff(hv * 0.70710678118654752f));
            gacc += ge * w2[e * H + j];
        }
        float gate = sigmf(gacc);
        float aw = g_aw[e];
        gs[tid] = gate * aw + (1.0f - aw);
    }
    __syncthreads();

    // V GEMM: C[128,128] = a[128,64] @ wv[e][64,128], scaled by gs per row
    int R = tid >> 4, Cg = tid & 15;            // 16 row-groups x 16 col-groups
    ull acc[8][4];
#pragma unroll
    for (int i = 0; i < 8; i++)
#pragma unroll
        for (int j = 0; j < 4; j++) acc[i][j] = 0ull;

    const float* wvb = wv + (size_t)e * S * DK + Cg * 8;
    const float* ab = a + (R * 8) * 65;
#pragma unroll 2
    for (int s = 0; s < S; s++) {
        float4 w0 = *(const float4*)(wvb + s * DK);
        float4 w1v = *(const float4*)(wvb + s * DK + 4);
        ull wp0 = pk2(w0.x, w0.y), wp1 = pk2(w0.z, w0.w);
        ull wp2 = pk2(w1v.x, w1v.y), wp3 = pk2(w1v.z, w1v.w);
#pragma unroll
        for (int i = 0; i < 8; i++) {
            float av = ab[i * 65 + s];
            ull ap = pk2(av, av);
            fma2(acc[i][0], ap, wp0);
            fma2(acc[i][1], ap, wp1);
            fma2(acc[i][2], ap, wp2);
            fma2(acc[i][3], ap, wp3);
        }
    }
#pragma unroll
    for (int i = 0; i < 8; i++) {
        int r = R * 8 + i;
        int p = sp[r >> 3];
        if (p < 0) continue;
        int b = r & 7, sl = ssl[r >> 3];
        float g = gs[r];
        float2 c0 = upk2(acc[i][0]), c1 = upk2(acc[i][1]);
        float2 c2 = upk2(acc[i][2]), c3 = upk2(acc[i][3]);
        float4* dst = (float4*)(g_V + ((((size_t)(b * P + p)) * 2 + sl) * DK + Cg * 8));
        dst[0] = make_float4(c0.x * g, c0.y * g, c1.x * g, c1.y * g);
        dst[1] = make_float4(c2.x * g, c2.y * g, c3.x * g, c3.y * g);
    }
}

// ---------------- K4: fused scalar per token (warp per token) ----------------
__global__ void __launch_bounds__(256) k_fused_k() {
    int warp = threadIdx.x >> 5, lane = threadIdx.x & 31;
    int tok = blockIdx.x * 8 + warp;
    int p = tok & (P - 1);
    float num = 0.0f;
#pragma unroll
    for (int slot = 0; slot < 2; slot++) {
        int e = g_pe[p * 2 + slot];
        if (e < 0) continue;
        const float* V = g_V + (((size_t)tok) * 2 + slot) * DK;
        float v0 = V[lane], v1 = V[lane + 32], v2 = V[lane + 64], v3 = V[lane + 96];
        float we = g_we[e];
        const float* dr = g_dirs + e * 5 * DK;
        float s = 0.0f;
#pragma unroll
        for (int v = 0; v < 5; v++) {
            const float* d = dr + v * DK;
            s += v0 * d[lane] + v1 * d[lane + 32] + v2 * d[lane + 64] + v3 * d[lane + 96];
        }
        num += we * s;
    }
#pragma unroll
    for (int o = 16; o; o >>= 1) num += __shfl_xor_sync(0xffffffffu, num, o);
    if (lane == 0) g_fused[tok] = num * (0.2f / g_den[p]) * g_invt;
}

// ---------------- K5: per-expert rec GEMM, out = x + rec on active slices ----------------
__global__ void __launch_bounds__(256, 2) k_rec(const float* __restrict__ x,
                                                const float* __restrict__ wout,
                                                float* __restrict__ out) {
    int e = blockIdx.y;
    int base = blockIdx.x * 16;
    int cnt = g_cnt[e];
    if (base >= cnt) return;

    extern __shared__ float sm[];
    float* Vt = sm;                // 128 * 133
    float* fs = sm + 128 * 133;    // 128
    __shared__ int sp[16];
    __shared__ int ssl[16];
    int tid = threadIdx.x;

    if (tid < 16) {
        int idx = base + tid;
        if (idx < cnt) {
            int v = g_list[e * P + idx];
            sp[tid] = v & 0xFFFF;
            ssl[tid] = v >> 16;
        } else { sp[tid] = -1; ssl[tid] = 0; }
    }
    __syncthreads();

    // stage V rows (128 x 128, pad 133) + fused per row
    {
        int r = tid >> 1, hf = tid & 1;
        int p = sp[r >> 3];
        float* vrow = Vt + r * 133 + hf * 64;
        if (p >= 0) {
            int b = r & 7, sl = ssl[r >> 3];
            const float4* src = (const float4*)(g_V + (((size_t)(b * P + p)) * 2 + sl) * DK) + hf * 16;
#pragma unroll
            for (int k = 0; k < 16; k++) {
                float4 w = src[k];
                vrow[k * 4 + 0] = w.x; vrow[k * 4 + 1] = w.y;
                vrow[k * 4 + 2] = w.z; vrow[k * 4 + 3] = w.w;
            }
            if (hf == 0) fs[r] = g_fused[b * P + p];
        } else {
#pragma unroll
            for (int k = 0; k < 64; k++) vrow[k] = 0.0f;
            if (hf == 0) fs[r] = 0.0f;
        }
    }
    __syncthreads();

    // rec GEMM: C[128,64] = Vt[128,128] @ wout[e][128,64]
    int R = tid >> 3, Cg = tid & 7;            // 32 row-groups x 8 col-groups
    ull acc[4][4];
#pragma unroll
    for (int i = 0; i < 4; i++)
#pragma unroll
        for (int j = 0; j < 4; j++) acc[i][j] = 0ull;

    const float* wb = wout + (size_t)e * DK * S + Cg * 8;
    const float* vb = Vt + (R * 4) * 133;
#pragma unroll 2
    for (int d = 0; d < DK; d++) {
        float4 w0 = *(const float4*)(wb + d * S);
        float4 w1v = *(const float4*)(wb + d * S + 4);
        ull wp0 = pk2(w0.x, w0.y), wp1 = pk2(w0.z, w0.w);
        ull wp2 = pk2(w1v.x, w1v.y), wp3 = pk2(w1v.z, w1v.w);
#pragma unroll
        for (int i = 0; i < 4; i++) {
            float av = vb[i * 133 + d];
            ull ap = pk2(av, av);
            fma2(acc[i][0], ap, wp0);
            fma2(acc[i][1], ap, wp1);
            fma2(acc[i][2], ap, wp2);
            fma2(acc[i][3], ap, wp3);
        }
    }
#pragma unroll
    for (int i = 0; i < 4; i++) {
        int r = R * 4 + i;
        int p = sp[r >> 3];
        if (p < 0) continue;
        int b = r & 7;
        float f = fs[r];
        size_t off = ((size_t)(b * P + p)) * D + e * S + Cg * 8;
        float4 x0 = *(const float4*)(x + off);
        float4 x1 = *(const float4*)(x + off + 4);
        float2 c0 = upk2(acc[i][0]), c1 = upk2(acc[i][1]);
        float2 c2 = upk2(acc[i][2]), c3 = upk2(acc[i][3]);
        float4 o0 = make_float4(x0.x + f * c0.x, x0.y + f * c0.y,
                                x0.z + f * c1.x, x0.w + f * c1.y);
        float4 o1 = make_float4(x1.x + f * c2.x, x1.y + f * c2.y,
                                x1.z + f * c3.x, x1.w + f * c3.y);
        *(float4*)(out + off) = o0;
        *(float4*)(out + off + 4) = o1;
    }
}

// ---------------- launch ----------------
extern "C" void kernel_launch(void* const* d_in, const int* in_sizes, int n_in,
                              void* d_out, int out_size) {
    const float* x     = (const float*)d_in[0];
    const float* fps   = (const float*)d_in[1];
    const float* gamma = (const float*)d_in[2];
    const float* beta  = (const float*)d_in[3];
    const float* w1    = (const float*)d_in[4];
    const float* b1    = (const float*)d_in[5];
    const float* w2    = (const float*)d_in[6];
    const float* b2    = (const float*)d_in[7];
    const float* alpha = (const float*)d_in[8];
    const float* wv    = (const float*)d_in[9];
    const float* penta = (const float*)d_in[10];
    const float* betas = (const float*)d_in[11];
    const float* wout  = (const float*)d_in[12];
    const float* pos   = (const float*)d_in[13];
    const float* temp  = (const float*)d_in[14];
    float* out = (float*)d_out;

    const int rec_smem = (128 * 133 + 128) * (int)sizeof(float);
    cudaFuncSetAttribute(k_rec, cudaFuncAttributeMaxDynamicSharedMemorySize, rec_smem);

    k_setup<<<1, 128>>>(alpha, betas, pos, penta, temp);
    k_bin<<<8, 256>>>(fps);
    k_ln<<<(B * P) / 8, 256>>>(x, gamma, beta, out);
    k_gatev<<<dim3(P / 16, E), 256>>>(w1, b1, w2, b2, wv);
    k_fused_k<<<(B * P) / 8, 256>>>();
    k_rec<<<dim3(P / 16, E), 256, rec_smem>>>(x, wout, out);
}

// round 4
// speedup vs baseline: 1.3570x; 1.3570x over previous
#include <cuda_runtime.h>

#define B 8
#define P 2048
#define D 1024
#define E 16
#define S 64
#define DK 128
#define H 16

typedef unsigned long long ull;

// ---------------- scratch (static device globals; no allocation) ----------------
__device__ float g_xa[(size_t)B * P * 2 * S];   // active-slice layernorm output (8 MB)
__device__ float g_V[(size_t)B * P * 2 * DK];   // per-(token,slot) V vectors (16 MB)
__device__ float g_fused[B * P];
__device__ float g_we[E];
__device__ float g_aw[E];
__device__ float g_invt;
__device__ float g_dirs[E * 5 * DK];
__device__ int   g_cnt[E];
__device__ int   g_list[E * P];                 // p | (slot<<16)
__device__ int   g_pe[P * 2];                   // active experts per p (-1 = none)
__device__ float g_den[P];

// ---------------- f32x2 packed-FMA helpers ----------------
__device__ __forceinline__ ull pk2(float lo, float hi) {
    ull r;
    asm("mov.b64 %0, {%1, %2};" : "=l"(r) : "f"(lo), "f"(hi));
    return r;
}
__device__ __forceinline__ void fma2(ull &c, ull a, ull b) {
    asm("fma.rn.f32x2 %0, %1, %2, %3;" : "=l"(c) : "l"(a), "l"(b), "l"(c));
}
__device__ __forceinline__ float2 upk2(ull v) {
    float lo, hi;
    asm("mov.b64 {%0, %1}, %2;" : "=f"(lo), "=f"(hi) : "l"(v));
    return make_float2(lo, hi);
}

__device__ __forceinline__ float sigmf(float x) { return 1.0f / (1.0f + expf(-x)); }

// ---------------- K0: per-expert scalars, dirs, zero counters ----------------
__global__ void k_setup(const float* __restrict__ alpha, const float* __restrict__ betas,
                        const float* __restrict__ pos_embed, const float* __restrict__ penta,
                        const float* __restrict__ temp) {
    int t = threadIdx.x;
    if (t < E) {
        g_cnt[t] = 0;
        g_aw[t] = sigmf(alpha[t]);
        float s = 0.0f;
        for (int d = 0; d < DK; d++) s += pos_embed[t * DK + d];
        float pw = sigmf(s * (1.0f / DK));
        const int offs[4] = {-2, -1, 1, 2};
        float vw = 0.0f; int vc = 0;
        for (int j = 0; j < 4; j++) {
            int nb = t + offs[j];
            if (nb >= 0 && nb < E) { vw += sigmf(betas[t * 4 + j]); vc++; }
        }
        g_we[t] = pw * (1.0f + vw / (float)vc);
    }
    if (t == 0) g_invt = 1.0f / fabsf(temp[0]);
    if (t < E * 5) {  // 80 dir rows
        const float* row = penta + (size_t)t * DK;
        float ss = 0.0f;
        for (int d = 0; d < DK; d++) ss += row[d] * row[d];
        float rn = rsqrtf(ss);
        for (int d = 0; d < DK; d++) g_dirs[t * DK + d] = row[d] * rn;
    }
}

// ---------------- K1: binning by fingerprint band ----------------
__global__ void k_bin(const float* __restrict__ fps) {
    int p = blockIdx.x * blockDim.x + threadIdx.x;
    if (p >= P) return;
    float fp = fps[p];
    int e0 = -1, e1 = -1;
    float den = 0.0f;
    for (int e = 0; e < E; e++) {
        float mn = fmaxf(0.0f, e * 0.0625f - 0.03125f);
        float mx = fminf(1.0f, (e + 1) * 0.0625f + 0.03125f);
        if (fp >= mn && fp < mx) {
            den += g_we[e];
            int slot;
            if (e0 < 0) { e0 = e; slot = 0; } else { e1 = e; slot = 1; }
            int pos = atomicAdd(&g_cnt[e], 1);
            g_list[e * P + pos] = p | (slot << 16);
        }
    }
    g_pe[p * 2] = e0;
    g_pe[p * 2 + 1] = e1;
    g_den[p] = fmaxf(den, 1e-6f);
}

// ---------------- K2: layernorm; out=x copy; write active xn slices ----------------
__global__ void __launch_bounds__(256) k_ln(const float* __restrict__ x,
                                            const float* __restrict__ gamma,
                                            const float* __restrict__ beta,
                                            float* __restrict__ out) {
    int warp = threadIdx.x >> 5, lane = threadIdx.x & 31;
    int tok = blockIdx.x * 8 + warp;          // 0..B*P-1
    const float4* xr = (const float4*)(x + (size_t)tok * D);
    float4 v[8];
    float sum = 0.0f;
#pragma unroll
    for (int k = 0; k < 8; k++) {
        v[k] = xr[k * 32 + lane];
        sum += v[k].x + v[k].y + v[k].z + v[k].w;
    }
#pragma unroll
    for (int o = 16; o; o >>= 1) sum += __shfl_xor_sync(0xffffffffu, sum, o);
    float mu = sum * (1.0f / D);
    float vs = 0.0f;
#pragma unroll
    for (int k = 0; k < 8; k++) {
        float dx = v[k].x - mu, dy = v[k].y - mu, dz = v[k].z - mu, dw = v[k].w - mu;
        vs += dx * dx + dy * dy + dz * dz + dw * dw;
    }
#pragma unroll
    for (int o = 16; o; o >>= 1) vs += __shfl_xor_sync(0xffffffffu, vs, o);
    float rstd = rsqrtf(vs * (1.0f / D) + 1e-5f);

    float4* orow = (float4*)(out + (size_t)tok * D);
#pragma unroll
    for (int k = 0; k < 8; k++) orow[k * 32 + lane] = v[k];   // residual base

    int p = tok & (P - 1);
#pragma unroll
    for (int slot = 0; slot < 2; slot++) {
        int e = g_pe[p * 2 + slot];
        if (e < 0) continue;
        int fbase = e * 16;              // float4 index of slice start
        int kk = fbase >> 5;
        int l0 = fbase & 31;
        if (lane >= l0 && lane < l0 + 16) {
            int f = fbase + (lane - l0);
            float4 xv = v[kk];
            float4 gm = ((const float4*)gamma)[f];
            float4 bt = ((const float4*)beta)[f];
            float4 o;
            o.x = (xv.x - mu) * rstd * gm.x + bt.x;
            o.y = (xv.y - mu) * rstd * gm.y + bt.y;
            o.z = (xv.z - mu) * rstd * gm.z + bt.z;
            o.w = (xv.w - mu) * rstd * gm.w + bt.w;
            ((float4*)g_xa)[((size_t)tok * 2 + slot) * 16 + (lane - l0)] = o;
        }
    }
}

// ---------------- K3: per-expert gate + V GEMM (gathered, smem-staged) ----------------
// smem: aT[64][128] (A transposed) | Ws[64][128] (wv tile) | w1s[64][16] | gs[128]
__global__ void __launch_bounds__(256, 2) k_gatev(const float* __restrict__ w1,
                                                  const float* __restrict__ b1,
                                                  const float* __restrict__ w2,
                                                  const float* __restrict__ b2,
                                                  const float* __restrict__ wv) {
    int e = blockIdx.y;
    int base = blockIdx.x * 16;
    int cnt = g_cnt[e];
    if (base >= cnt) return;

    extern __shared__ float sm[];
    float* aT  = sm;                  // 8192
    float* Ws  = sm + 8192;           // 8192
    float* w1s = sm + 16384;          // 1024
    float* gs  = sm + 17408;          // 128
    __shared__ int sp[16];
    __shared__ int ssl[16];
    int tid = threadIdx.x;

    if (tid < 16) {
        int idx = base + tid;
        if (idx < cnt) {
            int v = g_list[e * P + idx];
            sp[tid] = v & 0xFFFF;
            ssl[tid] = v >> 16;
        } else { sp[tid] = -1; ssl[tid] = 0; }
    }
    __syncthreads();

    // stage Ws (straight copy, layout already [s][col]) and w1s
    {
        const float4* src = (const float4*)(wv + (size_t)e * S * DK);
        float4* dst = (float4*)Ws;
#pragma unroll
        for (int k = 0; k < 8; k++) dst[tid + k * 256] = src[tid + k * 256];
        ((float4*)w1s)[tid] = ((const float4*)(w1 + (size_t)e * S * H))[tid];
    }
    // stage A transposed: aT[s][row]
    {
        int r = tid >> 1, hf = tid & 1;
        int p = sp[r >> 3];
        int s0 = hf * 32;
        if (p >= 0) {
            int b = r & 7, sl = ssl[r >> 3];
            const float4* src = (const float4*)(g_xa + (((size_t)(b * P + p)) * 2 + sl) * S) + hf * 8;
#pragma unroll
            for (int k = 0; k < 8; k++) {
                float4 v = src[k];
                aT[(s0 + k * 4 + 0) * 128 + r] = v.x;
                aT[(s0 + k * 4 + 1) * 128 + r] = v.y;
                aT[(s0 + k * 4 + 2) * 128 + r] = v.z;
                aT[(s0 + k * 4 + 3) * 128 + r] = v.w;
            }
        } else {
#pragma unroll
            for (int k = 0; k < 32; k++) aT[(s0 + k) * 128 + r] = 0.0f;
        }
    }
    __syncthreads();

    // alpha gate: one thread per row, weights broadcast from smem
    if (tid < 128) {
        float h[H];
#pragma unroll
        for (int j = 0; j < H; j++) h[j] = b1[e * H + j];
        for (int s = 0; s < S; s++) {
            float av = aT[s * 128 + tid];
            const float4* wr = (const float4*)(w1s + s * H);
            float4 q0 = wr[0], q1 = wr[1], q2 = wr[2], q3 = wr[3];
            h[0]  += av * q0.x; h[1]  += av * q0.y; h[2]  += av * q0.z; h[3]  += av * q0.w;
            h[4]  += av * q1.x; h[5]  += av * q1.y; h[6]  += av * q1.z; h[7]  += av * q1.w;
            h[8]  += av * q2.x; h[9]  += av * q2.y; h[10] += av * q2.z; h[11] += av * q2.w;
            h[12] += av * q3.x; h[13] += av * q3.y; h[14] += av * q3.z; h[15] += av * q3.w;
        }
        float gacc = b2[e];
#pragma unroll
        for (int j = 0; j < H; j++) {
            float hv = h[j];
            float ge = 0.5f * hv * (1.0f + erff(hv * 0.70710678118654752f));
            gacc += ge * w2[e * H + j];
        }
        float aw = g_aw[e];
        gs[tid] = sigmf(gacc) * aw + (1.0f - aw);
    }
    __syncthreads();

    // GEMM: C[128,128] = A[128,64] @ Ws[64,128]; row-pairs packed in f32x2
    int R = tid >> 4, Cg = tid & 15;
    ull acc[4][8];
#pragma unroll
    for (int i = 0; i < 4; i++)
#pragma unroll
        for (int j = 0; j < 8; j++) acc[i][j] = 0ull;

    const float* aTb = aT + R * 8;
    const float* Wb  = Ws + Cg * 8;
#pragma unroll 4
    for (int s = 0; s < S; s++) {
        const ull* ap = (const ull*)(aTb + s * 128);
        ull a0 = ap[0], a1 = ap[1], a2 = ap[2], a3 = ap[3];
        float4 u0 = *(const float4*)(Wb + s * 128);
        float4 u1 = *(const float4*)(Wb + s * 128 + 4);
        ull w0 = pk2(u0.x, u0.x), w1p = pk2(u0.y, u0.y);
        ull w2p = pk2(u0.z, u0.z), w3 = pk2(u0.w, u0.w);
        ull w4 = pk2(u1.x, u1.x), w5 = pk2(u1.y, u1.y);
        ull w6 = pk2(u1.z, u1.z), w7 = pk2(u1.w, u1.w);
        fma2(acc[0][0], a0, w0); fma2(acc[0][1], a0, w1p); fma2(acc[0][2], a0, w2p); fma2(acc[0][3], a0, w3);
        fma2(acc[0][4], a0, w4); fma2(acc[0][5], a0, w5);  fma2(acc[0][6], a0, w6);  fma2(acc[0][7], a0, w7);
        fma2(acc[1][0], a1, w0); fma2(acc[1][1], a1, w1p); fma2(acc[1][2], a1, w2p); fma2(acc[1][3], a1, w3);
        fma2(acc[1][4], a1, w4); fma2(acc[1][5], a1, w5);  fma2(acc[1][6], a1, w6);  fma2(acc[1][7], a1, w7);
        fma2(acc[2][0], a2, w0); fma2(acc[2][1], a2, w1p); fma2(acc[2][2], a2, w2p); fma2(acc[2][3], a2, w3);
        fma2(acc[2][4], a2, w4); fma2(acc[2][5], a2, w5);  fma2(acc[2][6], a2, w6);  fma2(acc[2][7], a2, w7);
        fma2(acc[3][0], a3, w0); fma2(acc[3][1], a3, w1p); fma2(acc[3][2], a3, w2p); fma2(acc[3][3], a3, w3);
        fma2(acc[3][4], a3, w4); fma2(acc[3][5], a3, w5);  fma2(acc[3][6], a3, w6);  fma2(acc[3][7], a3, w7);
    }

    // epilogue: scale by gate, scatter rows (16 threads per row -> coalesced 512B)
#pragma unroll
    for (int ri = 0; ri < 4; ri++) {
        float2 u[8];
#pragma unroll
        for (int c = 0; c < 8; c++) u[c] = upk2(acc[ri][c]);
#pragma unroll
        for (int half = 0; half < 2; half++) {
            int r = R * 8 + ri * 2 + half;
            int en = r >> 3;
            int p = sp[en];
            if (p < 0) continue;
            int b = r & 7, sl = ssl[en];
            float g = gs[r];
            float* dst = g_V + ((((size_t)(b * P + p)) * 2 + sl) * DK + Cg * 8);
            if (half == 0) {
                *(float4*)dst       = make_float4(u[0].x * g, u[1].x * g, u[2].x * g, u[3].x * g);
                *(float4*)(dst + 4) = make_float4(u[4].x * g, u[5].x * g, u[6].x * g, u[7].x * g);
            } else {
                *(float4*)dst       = make_float4(u[0].y * g, u[1].y * g, u[2].y * g, u[3].y * g);
                *(float4*)(dst + 4) = make_float4(u[4].y * g, u[5].y * g, u[6].y * g, u[7].y * g);
            }
        }
    }
}

// ---------------- K4: fused scalar per token (warp per token) ----------------
__global__ void __launch_bounds__(256) k_fused_k() {
    int warp = threadIdx.x >> 5, lane = threadIdx.x & 31;
    int tok = blockIdx.x * 8 + warp;
    int p = tok & (P - 1);
    float num = 0.0f;
#pragma unroll
    for (int slot = 0; slot < 2; slot++) {
        int e = g_pe[p * 2 + slot];
        if (e < 0) continue;
        const float* V = g_V + (((size_t)tok) * 2 + slot) * DK;
        float v0 = V[lane], v1 = V[lane + 32], v2 = V[lane + 64], v3 = V[lane + 96];
        float we = g_we[e];
        const float* dr = g_dirs + e * 5 * DK;
        float s = 0.0f;
#pragma unroll
        for (int v = 0; v < 5; v++) {
            const float* d = dr + v * DK;
            s += v0 * d[lane] + v1 * d[lane + 32] + v2 * d[lane + 64] + v3 * d[lane + 96];
        }
        num += we * s;
    }
#pragma unroll
    for (int o = 16; o; o >>= 1) num += __shfl_xor_sync(0xffffffffu, num, o);
    if (lane == 0) g_fused[tok] = num * (0.2f / g_den[p]) * g_invt;
}

// ---------------- K5: per-expert rec GEMM (smem-staged), out = x + f*rec ----------------
// smem: Vt[128][128] (V transposed) | Ws[128][64] (wout tile) | fs[128]
__global__ void __launch_bounds__(256, 2) k_rec(const float* __restrict__ x,
                                                const float* __restrict__ wout,
                                                float* __restrict__ out) {
    int e = blockIdx.y;
    int base = blockIdx.x * 16;
    int cnt = g_cnt[e];
    if (base >= cnt) return;

    extern __shared__ float sm[];
    float* Vt = sm;               // 16384
    float* Ws = sm + 16384;       // 8192
    float* fs = sm + 24576;       // 128
    __shared__ int sp[16];
    __shared__ int ssl[16];
    int tid = threadIdx.x;

    if (tid < 16) {
        int idx = base + tid;
        if (idx < cnt) {
            int v = g_list[e * P + idx];
            sp[tid] = v & 0xFFFF;
            ssl[tid] = v >> 16;
        } else { sp[tid] = -1; ssl[tid] = 0; }
    }
    __syncthreads();

    // stage Ws (straight copy, wout layout [d][col])
    {
        const float4* src = (const float4*)(wout + (size_t)e * DK * S);
        float4* dst = (float4*)Ws;
#pragma unroll
        for (int k = 0; k < 8; k++) dst[tid + k * 256] = src[tid + k * 256];
    }
    // stage Vt transposed: Vt[d][row] + fused per row
    {
        int r = tid >> 1, hf = tid & 1;
        int p = sp[r >> 3];
        int d0 = hf * 64;
        if (p >= 0) {
            int b = r & 7, sl = ssl[r >> 3];
            const float4* src = (const float4*)(g_V + (((size_t)(b * P + p)) * 2 + sl) * DK) + hf * 16;
#pragma unroll
            for (int k = 0; k < 16; k++) {
                float4 v = src[k];
                Vt[(d0 + k * 4 + 0) * 128 + r] = v.x;
                Vt[(d0 + k * 4 + 1) * 128 + r] = v.y;
                Vt[(d0 + k * 4 + 2) * 128 + r] = v.z;
                Vt[(d0 + k * 4 + 3) * 128 + r] = v.w;
            }
            if (hf == 0) fs[r] = g_fused[b * P + p];
        } else {
#pragma unroll
            for (int k = 0; k < 64; k++) Vt[(d0 + k) * 128 + r] = 0.0f;
            if (hf == 0) fs[r] = 0.0f;
        }
    }
    __syncthreads();

    // GEMM: C[128,64] = V[128,128] @ Ws[128,64]; row-pairs packed
    int R = tid >> 4, Cg = tid & 15;   // 16 row-groups(8) x 16 col-groups(4)
    ull acc[4][4];
#pragma unroll
    for (int i = 0; i < 4; i++)
#pragma unroll
        for (int j = 0; j < 4; j++) acc[i][j] = 0ull;

    const float* Vb = Vt + R * 8;
    const float* Wb = Ws + Cg * 4;
#pragma unroll 4
    for (int d = 0; d < DK; d++) {
        const ull* ap = (const ull*)(Vb + d * 128);
        ull a0 = ap[0], a1 = ap[1], a2 = ap[2], a3 = ap[3];
        float4 u = *(const float4*)(Wb + d * 64);
        ull w0 = pk2(u.x, u.x), w1p = pk2(u.y, u.y);
        ull w2p = pk2(u.z, u.z), w3 = pk2(u.w, u.w);
        fma2(acc[0][0], a0, w0); fma2(acc[0][1], a0, w1p); fma2(acc[0][2], a0, w2p); fma2(acc[0][3], a0, w3);
        fma2(acc[1][0], a1, w0); fma2(acc[1][1], a1, w1p); fma2(acc[1][2], a1, w2p); fma2(acc[1][3], a1, w3);
        fma2(acc[2][0], a2, w0); fma2(acc[2][1], a2, w1p); fma2(acc[2][2], a2, w2p); fma2(acc[2][3], a2, w3);
        fma2(acc[3][0], a3, w0); fma2(acc[3][1], a3, w1p); fma2(acc[3][2], a3, w2p); fma2(acc[3][3], a3, w3);
    }

    // epilogue: out = x + f * rec on active slice cols [Cg*4, Cg*4+4)
#pragma unroll
    for (int ri = 0; ri < 4; ri++) {
        float2 u[4];
#pragma unroll
        for (int c = 0; c < 4; c++) u[c] = upk2(acc[ri][c]);
#pragma unroll
        for (int half = 0; half < 2; half++) {
            int r = R * 8 + ri * 2 + half;
            int en = r >> 3;
            int p = sp[en];
            if (p < 0) continue;
            int b = r & 7;
            float f = fs[r];
            size_t off = ((size_t)(b * P + p)) * D + e * S + Cg * 4;
            float4 xv = *(const float4*)(x + off);
            float4 o;
            if (half == 0) {
                o = make_float4(xv.x + f * u[0].x, xv.y + f * u[1].x,
                                xv.z + f * u[2].x, xv.w + f * u[3].x);
            } else {
                o = make_float4(xv.x + f * u[0].y, xv.y + f * u[1].y,
                                xv.z + f * u[2].y, xv.w + f * u[3].y);
            }
            *(float4*)(out + off) = o;
        }
    }
}

// ---------------- launch ----------------
extern "C" void kernel_launch(void* const* d_in, const int* in_sizes, int n_in,
                              void* d_out, int out_size) {
    const float* x     = (const float*)d_in[0];
    const float* fps   = (const float*)d_in[1];
    const float* gamma = (const float*)d_in[2];
    const float* beta  = (const float*)d_in[3];
    const float* w1    = (const float*)d_in[4];
    const float* b1    = (const float*)d_in[5];
    const float* w2    = (const float*)d_in[6];
    const float* b2    = (const float*)d_in[7];
    const float* alpha = (const float*)d_in[8];
    const float* wv    = (const float*)d_in[9];
    const float* penta = (const float*)d_in[10];
    const float* betas = (const float*)d_in[11];
    const float* wout  = (const float*)d_in[12];
    const float* pos   = (const float*)d_in[13];
    const float* temp  = (const float*)d_in[14];
    float* out = (float*)d_out;

    const int gatev_smem = (8192 + 8192 + 1024 + 128) * (int)sizeof(float);  // ~70 KB
    const int rec_smem   = (16384 + 8192 + 128) * (int)sizeof(float);        // ~99 KB
    static int attr_done = 0;
    if (!attr_done) {
        cudaFuncSetAttribute(k_gatev, cudaFuncAttributeMaxDynamicSharedMemorySize, gatev_smem);
        cudaFuncSetAttribute(k_rec,   cudaFuncAttributeMaxDynamicSharedMemorySize, rec_smem);
        attr_done = 1;
    }

    k_setup<<<1, 128>>>(alpha, betas, pos, penta, temp);
    k_bin<<<8, 256>>>(fps);
    k_ln<<<(B * P) / 8, 256>>>(x, gamma, beta, out);
    k_gatev<<<dim3(P / 16, E), 256, gatev_smem>>>(w1, b1, w2, b2, wv);
    k_fused_k<<<(B * P) / 8, 256>>>();
    k_rec<<<dim3(P / 16, E), 256, rec_smem>>>(x, wout, out);
}